// round 17
// baseline (speedup 1.0000x reference)
#include <cuda_runtime.h>
#include <cuda_bf16.h>
#include <math.h>
#include <stdint.h>

// Problem constants
#define BQ   512
#define KT   64
#define EBD  256
#define VFD  512
#define SENS 768
#define H0   512
#define H1   256
#define H2   64
#define C0   1280
#define C1   768
#define C2   320

// queue geometry (64-row tiles):
//  prologue: Cin t=0..3 -> 4 x 128 = 512 items
//  slot s (0..65): Cin(s+4) 128 | L0(s) 128 | L1(s-1) 64 | L2(s-2) 16 = 336
#define QSLOT 336
#define QTOT  (512 + 66 * QSLOT)

// ---------------- device scratch (static, no allocation) ----------------
__device__ __align__(16) __nv_bfloat16 Xh[(size_t)BQ * KT * SENS];
__device__ __align__(16) __nv_bfloat16 Xl[(size_t)BQ * KT * SENS];
// Weights: [3*hid][cat] rows interleaved {ff1, ff2, ta+tb}, k contiguous.
__device__ __align__(16) __nv_bfloat16 W0h[(size_t)3 * H0 * C0];
__device__ __align__(16) __nv_bfloat16 W0l[(size_t)3 * H0 * C0];
__device__ __align__(16) __nv_bfloat16 W1h[(size_t)3 * H1 * C1];
__device__ __align__(16) __nv_bfloat16 W1l[(size_t)3 * H1 * C1];
__device__ __align__(16) __nv_bfloat16 W2h[(size_t)3 * H2 * C2];
__device__ __align__(16) __nv_bfloat16 W2l[(size_t)3 * H2 * C2];
__device__ __align__(16) __nv_bfloat16 h0h[2][BQ * H0];
__device__ __align__(16) __nv_bfloat16 h0l[2][BQ * H0];
__device__ __align__(16) __nv_bfloat16 h1h[2][BQ * H1];
__device__ __align__(16) __nv_bfloat16 h1l[2][BQ * H1];
__device__ __align__(16) __nv_bfloat16 h2h[2][BQ * H2];
__device__ __align__(16) __nv_bfloat16 h2l[2][BQ * H2];
// precomputed input-GEMM partials: Cin[t][512 rows][1536 cols] fp32
__device__ float CinG[(size_t)KT * BQ * 3 * H0];
// merged time-scale biases
__device__ float bts0[H0], bts1[H1], bts2[H2];
// scheduler state (8 row-groups of 64)
__device__ int qhead;
__device__ int cCin[KT * 8];
__device__ int cL0[KT * 8];
__device__ int cL1[KT * 8];
__device__ int cL2[KT * 8];

// ---------------- helpers ----------------
__device__ __forceinline__ void bf16_split(float v, __nv_bfloat16& hi, __nv_bfloat16& lo)
{
    hi = __float2bfloat16(v);
    lo = __float2bfloat16(v - __bfloat162float(hi));
}

__device__ __forceinline__ void mma_bf16(float* d, const uint32_t* a, const uint32_t* b)
{
    asm volatile(
        "mma.sync.aligned.m16n8k16.row.col.f32.bf16.bf16.f32 "
        "{%0,%1,%2,%3}, {%4,%5,%6,%7}, {%8,%9}, {%0,%1,%2,%3};\n"
        : "+f"(d[0]), "+f"(d[1]), "+f"(d[2]), "+f"(d[3])
        : "r"(a[0]), "r"(a[1]), "r"(a[2]), "r"(a[3]),
          "r"(b[0]), "r"(b[1]));
}

__device__ __forceinline__ void cpa16(uint32_t* dst_smem, const void* src_gmem)
{
    uint32_t d = (uint32_t)__cvta_generic_to_shared(dst_smem);
    asm volatile("cp.async.cg.shared.global [%0], [%1], 16;\n" :: "r"(d), "l"(src_gmem));
}

#define LDSM4(r0, r1, r2, r3, a) \
    asm volatile("ldmatrix.sync.aligned.m8n8.x4.shared.b16 {%0,%1,%2,%3}, [%4];" \
                 : "=r"(r0), "=r"(r1), "=r"(r2), "=r"(r3) : "r"(a))

__device__ __forceinline__ void wait_cnt(const int* p, int target)
{
    for (;;) {
        int v;
        asm volatile("ld.acquire.gpu.global.b32 %0, [%1];" : "=r"(v) : "l"(p));
        if (v >= target) break;
        __nanosleep(128);
    }
}

__device__ __forceinline__ void release_cnt(int* p)
{
    asm volatile("red.release.gpu.global.add.s32 [%0], 1;" :: "l"(p) : "memory");
}

// ---------------- prep kernels ----------------
__global__ void prep_sched()
{
    int i = blockIdx.x * blockDim.x + threadIdx.x;
    if (i == 0) qhead = 0;
    if (i < KT * 8) { cCin[i] = 0; cL0[i] = 0; cL1[i] = 0; cL2[i] = 0; }
}

__global__ void prep_weights3(const float* __restrict__ ff1, const float* __restrict__ ff2,
                              const float* __restrict__ ta,  const float* __restrict__ tb,
                              const float* __restrict__ mask,
                              __nv_bfloat16* __restrict__ dh, __nv_bfloat16* __restrict__ dl,
                              int hid, int cat)
{
    int idx = blockIdx.x * blockDim.x + threadIdx.x;
    if (idx >= hid * cat) return;
    int j = idx / cat;
    int k = idx - j * cat;
    float m = mask[idx];
    float v[3] = { ff1[idx] * m, ff2[idx] * m, ta[idx] + tb[idx] };
    #pragma unroll
    for (int q = 0; q < 3; q++) {
        __nv_bfloat16 hi, lo;
        bf16_split(v[q], hi, lo);
        size_t o = (size_t)(3 * j + q) * cat + k;
        dh[o] = hi; dl[o] = lo;
    }
}

__global__ void prep_inputs_bf(const float* __restrict__ base, const float* __restrict__ vis,
                               __nv_bfloat16* __restrict__ xh, __nv_bfloat16* __restrict__ xl)
{
    size_t idx = (size_t)blockIdx.x * blockDim.x + threadIdx.x;
    if (idx >= (size_t)BQ * KT * SENS) return;
    size_t row = idx / SENS;
    int c = (int)(idx - row * SENS);
    float v = (c < EBD) ? base[row * EBD + c] : vis[row * VFD + (c - EBD)];
    __nv_bfloat16 hi, lo;
    bf16_split(v, hi, lo);
    xh[idx] = hi; xl[idx] = lo;
}

__global__ void prep_bts(const float* __restrict__ ta0, const float* __restrict__ tb0,
                         const float* __restrict__ ta1, const float* __restrict__ tb1,
                         const float* __restrict__ ta2, const float* __restrict__ tb2)
{
    int i = blockIdx.x * blockDim.x + threadIdx.x;
    if (i < H0) bts0[i] = ta0[i] + tb0[i];
    if (i < H1) bts1[i] = ta1[i] + tb1[i];
    if (i < H2) bts2[i] = ta2[i] + tb2[i];
}

__global__ void extract_out(const __nv_bfloat16* __restrict__ hh,
                            const __nv_bfloat16* __restrict__ hl,
                            float* __restrict__ out, int n)
{
    int i = blockIdx.x * blockDim.x + threadIdx.x;
    if (i < n) out[i] = __bfloat162float(hh[i]) + __bfloat162float(hl[i]);
}

// ---------------- shared GEMM core (3xBF16, m16n8k16, 64x96 tile) ----------------
// acc += A[64 rows, klen] @ W[klen, 96 cols]  (W rows k-contig at kstride).
// 128 thr = 4 warps as 2(M) x 2(N); warp tile 32 x 48 (MT=2, NT=6).
#define RS   20
#define APL  (64 * RS)                  // 1280 u32
#define BPL  (96 * RS)                  // 1920 u32
#define BUFSZ (2 * APL + 2 * BPL)       // 6400 u32
#define CS   100

__device__ __forceinline__ void gemm_acc(uint32_t* sm32, float acc[2][6][4],
                                         int rowBase, int colBase,
                                         const __nv_bfloat16* s0h, const __nv_bfloat16* s0l,
                                         int st0, int len0,
                                         const __nv_bfloat16* s1h, const __nv_bfloat16* s1l,
                                         int st1,
                                         const __nv_bfloat16* Wh, const __nv_bfloat16* Wl,
                                         int kstride, int klen)
{
    const int tid  = threadIdx.x;
    const int lane = tid & 31;
    const int wid  = tid >> 5;
    const int wm   = wid & 1;
    const int wn   = wid >> 1;

    const uint32_t smemB = (uint32_t)__cvta_generic_to_shared(sm32);
    const int aLaneRow = (lane & 7) + ((lane >> 3) & 1) * 8;
    const int aKoff    = ((lane >> 4) & 1) * 16;
    const int bLaneRow = (lane & 7) + ((lane >> 4) & 1) * 8;
    const int bKoff    = ((lane >> 3) & 1) * 16;
    const uint32_t aBaseOff = (uint32_t)((wm * 32 + aLaneRow) * (RS * 4) + aKoff);
    const uint32_t bBaseOff = (uint32_t)((wn * 48 + bLaneRow) * (RS * 4) + bKoff);

    auto load_tiles = [&](int k0, int buf) {
        const __nv_bfloat16 *shi, *slo; int ss, so;
        if (k0 < len0) { shi = s0h; slo = s0l; ss = st0; so = k0; }
        else           { shi = s1h; slo = s1l; ss = st1; so = k0 - len0; }
        uint32_t* bb = sm32 + buf * BUFSZ;
        #pragma unroll
        for (int i = 0; i < 2; i++) {   // A: 64 rows x 4 chunks = 256
            int idx = tid + i * 128;
            int r = idx >> 2, c = idx & 3;
            size_t go = (size_t)(rowBase + r) * ss + so + c * 8;
            cpa16(bb + r * RS + c * 4, shi + go);
            cpa16(bb + APL + r * RS + c * 4, slo + go);
        }
        #pragma unroll
        for (int i = 0; i < 3; i++) {   // B: 96 rows x 4 chunks = 384
            int idx = tid + i * 128;
            int r = idx >> 2, c = idx & 3;
            size_t go = (size_t)(colBase + r) * kstride + k0 + c * 8;
            cpa16(bb + 2 * APL + r * RS + c * 4, Wh + go);
            cpa16(bb + 2 * APL + BPL + r * RS + c * 4, Wl + go);
        }
        asm volatile("cp.async.commit_group;\n");
    };

    load_tiles(0, 0);

    const int ntile = klen / 32;
    int buf = 0;
    for (int it = 0; it < ntile; it++, buf ^= 1) {
        if (it + 1 < ntile) {
            load_tiles((it + 1) * 32, buf ^ 1);
            asm volatile("cp.async.wait_group 1;\n");
        } else {
            asm volatile("cp.async.wait_group 0;\n");
        }
        __syncthreads();

        const uint32_t bufB = smemB + (uint32_t)(buf * BUFSZ) * 4;
        const uint32_t aHi = bufB + aBaseOff;
        const uint32_t aLo = bufB + (uint32_t)APL * 4 + aBaseOff;
        const uint32_t bHi = bufB + (uint32_t)(2 * APL) * 4 + bBaseOff;
        const uint32_t bLo = bufB + (uint32_t)(2 * APL + BPL) * 4 + bBaseOff;

        #pragma unroll
        for (int k16 = 0; k16 < 2; k16++) {
            const uint32_t ko = (uint32_t)(k16 * 32);
            uint32_t ah[2][4], al[2][4];
            #pragma unroll
            for (int mt = 0; mt < 2; mt++) {
                LDSM4(ah[mt][0], ah[mt][1], ah[mt][2], ah[mt][3],
                      aHi + mt * 16 * (RS * 4) + ko);
                LDSM4(al[mt][0], al[mt][1], al[mt][2], al[mt][3],
                      aLo + mt * 16 * (RS * 4) + ko);
            }
            uint32_t bh[6][2], bl[6][2];
            #pragma unroll
            for (int p = 0; p < 3; p++) {
                LDSM4(bh[2 * p][0], bh[2 * p][1], bh[2 * p + 1][0], bh[2 * p + 1][1],
                      bHi + p * 16 * (RS * 4) + ko);
                LDSM4(bl[2 * p][0], bl[2 * p][1], bl[2 * p + 1][0], bl[2 * p + 1][1],
                      bLo + p * 16 * (RS * 4) + ko);
            }
            #pragma unroll
            for (int mt = 0; mt < 2; mt++)
                #pragma unroll
                for (int nt = 0; nt < 6; nt++) mma_bf16(acc[mt][nt], ah[mt], bh[nt]);
            #pragma unroll
            for (int mt = 0; mt < 2; mt++)
                #pragma unroll
                for (int nt = 0; nt < 6; nt++) mma_bf16(acc[mt][nt], ah[mt], bl[nt]);
            #pragma unroll
            for (int mt = 0; mt < 2; mt++)
                #pragma unroll
                for (int nt = 0; nt < 6; nt++) mma_bf16(acc[mt][nt], al[mt], bh[nt]);
        }
        __syncthreads();
    }
}

// stage acc fragments into Cs (fp32, 64 x 96, stride CS)
__device__ __forceinline__ void stage_acc(uint32_t* sm32, float acc[2][6][4])
{
    const int tid  = threadIdx.x;
    const int lane = tid & 31;
    const int wid  = tid >> 5;
    const int wm   = wid & 1;
    const int wn   = wid >> 1;
    const int g    = lane >> 2;
    const int tc   = lane & 3;
    float* Cs = reinterpret_cast<float*>(sm32);
    const int cb = wn * 48 + 2 * tc;
    #pragma unroll
    for (int mt = 0; mt < 2; mt++) {
        const int r0 = wm * 32 + mt * 16 + g;
        #pragma unroll
        for (int nt = 0; nt < 6; nt++) {
            const int c = cb + nt * 8;
            *reinterpret_cast<float2*>(&Cs[r0 * CS + c])       = make_float2(acc[mt][nt][0], acc[mt][nt][1]);
            *reinterpret_cast<float2*>(&Cs[(r0 + 8) * CS + c]) = make_float2(acc[mt][nt][2], acc[mt][nt][3]);
        }
    }
}

// ---------------- Cin tile: pure GEMM, fp32 store ----------------
__device__ void cin_tile(uint32_t* sm32, int t, int bx, int by)
{
    float acc[2][6][4];
    #pragma unroll
    for (int m = 0; m < 2; m++)
        #pragma unroll
        for (int q = 0; q < 6; q++)
            #pragma unroll
            for (int z = 0; z < 4; z++) acc[m][q][z] = 0.0f;

    const int rowBase = bx * 64;
    const int colBase = by * 96;
    gemm_acc(sm32, acc, rowBase, colBase,
             Xh + (size_t)t * SENS, Xl + (size_t)t * SENS, KT * SENS, SENS,
             Xh + (size_t)t * SENS, Xl + (size_t)t * SENS, KT * SENS,
             W0h, W0l, C0, SENS);

    stage_acc(sm32, acc);
    __syncthreads();

    const float* Cs = reinterpret_cast<const float*>(sm32);
    float* dst = CinG + (size_t)t * BQ * 3 * H0;
    const int tid = threadIdx.x;
    #pragma unroll
    for (int i = 0; i < 12; i++) {
        int o = tid + i * 128;           // 1536 float4s
        int r = o / 24, c4 = o % 24;
        float4 v = make_float4(Cs[r * CS + c4 * 4 + 0], Cs[r * CS + c4 * 4 + 1],
                               Cs[r * CS + c4 * 4 + 2], Cs[r * CS + c4 * 4 + 3]);
        *reinterpret_cast<float4*>(&dst[(size_t)(rowBase + r) * (3 * H0) + colBase + c4 * 4]) = v;
    }
}

// ---------------- CfC tile: GEMM + epilogue (optional Cin partial add) ----------------
__device__ void cfc_tile(uint32_t* sm32, int bx, int by,
                         const __nv_bfloat16* s0h, const __nv_bfloat16* s0l, int st0, int len0,
                         const __nv_bfloat16* s1h, const __nv_bfloat16* s1l, int st1,
                         const __nv_bfloat16* Wh, const __nv_bfloat16* Wl,
                         int kstride, int klen,
                         const float* __restrict__ bff1, const float* __restrict__ bff2,
                         const float* __restrict__ bts,
                         const float* __restrict__ cinp,   // nullptr or Cin[t] base
                         int hid,
                         __nv_bfloat16* __restrict__ oh, __nv_bfloat16* __restrict__ ol)
{
    float acc[2][6][4];
    #pragma unroll
    for (int m = 0; m < 2; m++)
        #pragma unroll
        for (int q = 0; q < 6; q++)
            #pragma unroll
            for (int z = 0; z < 4; z++) acc[m][q][z] = 0.0f;

    const int rowBase = bx * 64;
    const int colBase = by * 96;
    gemm_acc(sm32, acc, rowBase, colBase, s0h, s0l, st0, len0, s1h, s1l, st1,
             Wh, Wl, kstride, klen);

    stage_acc(sm32, acc);
    __syncthreads();

    const float* Cs = reinterpret_cast<const float*>(sm32);
    const int jBase = colBase / 3;
    const int tid = threadIdx.x;
    #pragma unroll
    for (int i = 0; i < 16; i++) {
        int o  = tid + i * 128;          // 0..2047
        int r  = o >> 5;                 // 0..63
        int jj = o & 31;
        float c0 = Cs[r * CS + 3 * jj + 0];
        float c1 = Cs[r * CS + 3 * jj + 1];
        float c2 = Cs[r * CS + 3 * jj + 2];
        if (cinp) {
            const float* cp = cinp + (size_t)(rowBase + r) * (3 * H0) + colBase + 3 * jj;
            c0 += __ldg(cp + 0);
            c1 += __ldg(cp + 1);
            c2 += __ldg(cp + 2);
        }
        int j = jBase + jj;
        float f1 = tanhf(c0 + bff1[j]);
        float f2 = tanhf(c1 + bff2[j]);
        float ti = 1.0f / (1.0f + expf(-(c2 + bts[j])));
        float v  = f1 + ti * (f2 - f1);
        __nv_bfloat16 hi, lo; bf16_split(v, hi, lo);
        oh[(size_t)(rowBase + r) * hid + j] = hi;
        ol[(size_t)(rowBase + r) * hid + j] = lo;
    }
}

// ---------------- persistent dataflow kernel ----------------
// 592 worker CTAs drain a queue mixing recurrence tiles with independent
// input-GEMM (Cin) filler tiles; counters at (t, 64-row group) grain.
__global__ __launch_bounds__(128, 4)
void cfc_persist(const float* __restrict__ b0f1, const float* __restrict__ b0f2,
                 const float* __restrict__ b1f1, const float* __restrict__ b1f2,
                 const float* __restrict__ b2f1, const float* __restrict__ b2f2)
{
    extern __shared__ __align__(16) uint32_t sm32[];
    __shared__ int s_item;
    const int tid = threadIdx.x;

    for (;;) {
        if (tid == 0) s_item = atomicAdd(&qhead, 1);
        __syncthreads();
        const int g = s_item;
        __syncthreads();
        if (g >= QTOT) break;

        int layer, t, bx, by;
        if (g < 512) {
            layer = 3; t = g >> 7;
            int r = g & 127; bx = r >> 4; by = r & 15;
        } else {
            int G = g - 512;
            int s = G / QSLOT;
            int r = G - s * QSLOT;
            if (r < 128)      { layer = 3; t = s + 4; bx = r >> 4;         by = r & 15; }
            else if (r < 256) { layer = 0; t = s;     bx = (r - 128) >> 4; by = (r - 128) & 15; }
            else if (r < 320) { layer = 1; t = s - 1; bx = (r - 256) >> 3; by = (r - 256) & 7; }
            else              { layer = 2; t = s - 2; bx = (r - 320) >> 1; by = (r - 320) & 1; }
        }
        if (t < 0 || t >= KT) continue;

        const int pi = t & 1, po = pi ^ 1;

        if (layer == 3) {
            cin_tile(sm32, t, bx, by);
            __threadfence();
            __syncthreads();
            if (tid == 0) release_cnt(&cCin[t * 8 + bx]);
        } else if (layer == 0) {
            if (tid == 0) {
                wait_cnt(&cCin[t * 8 + bx], 16);                    // input partial ready
                if (t >= 1) wait_cnt(&cL0[(t - 1) * 8 + bx], 16);   // RAW h0 prev
                if (t >= 2) wait_cnt(&cL1[(t - 2) * 8 + bx], 8);    // WAR h0 slot reuse
            }
            __syncthreads();
            cfc_tile(sm32, bx, by,
                     h0h[pi], h0l[pi], H0, H0,
                     h0h[pi], h0l[pi], H0,
                     W0h + SENS, W0l + SENS, C0, H0,
                     b0f1, b0f2, bts0,
                     CinG + (size_t)t * BQ * 3 * H0,
                     H0, h0h[po], h0l[po]);
            __threadfence();
            __syncthreads();
            if (tid == 0) release_cnt(&cL0[t * 8 + bx]);
        } else if (layer == 1) {
            if (tid == 0) {
                wait_cnt(&cL0[t * 8 + bx], 16);                     // RAW h0 new
                if (t >= 1) wait_cnt(&cL1[(t - 1) * 8 + bx], 8);    // RAW h1 prev
                if (t >= 2) wait_cnt(&cL2[(t - 2) * 8 + bx], 2);    // WAR h1 slot reuse
            }
            __syncthreads();
            cfc_tile(sm32, bx, by,
                     h0h[po], h0l[po], H0, H0,
                     h1h[pi], h1l[pi], H1,
                     W1h, W1l, C1, C1,
                     b1f1, b1f2, bts1,
                     (const float*)nullptr,
                     H1, h1h[po], h1l[po]);
            __threadfence();
            __syncthreads();
            if (tid == 0) release_cnt(&cL1[t * 8 + bx]);
        } else {
            if (tid == 0) {
                wait_cnt(&cL1[t * 8 + bx], 8);                      // RAW h1 new
                if (t >= 1) wait_cnt(&cL2[(t - 1) * 8 + bx], 2);    // RAW h2 prev (+WAR)
            }
            __syncthreads();
            cfc_tile(sm32, bx, by,
                     h1h[po], h1l[po], H1, H1,
                     h2h[pi], h2l[pi], H2,
                     W2h, W2l, C2, C2,
                     b2f1, b2f2, bts2,
                     (const float*)nullptr,
                     H2, h2h[po], h2l[po]);
            __threadfence();
            __syncthreads();
            if (tid == 0) release_cnt(&cL2[t * 8 + bx]);
        }
    }
}

// dynamic smem: 2 buf x 6400 u32 x 4 B = 51200 (>= Cs staging 64*100*4 = 25600)
#define SMF 51200

// ---------------- host launcher ----------------
extern "C" void kernel_launch(void* const* d_in, const int* in_sizes, int n_in,
                              void* d_out, int out_size)
{
    const float* base = (const float*)d_in[0];
    const float* vis  = (const float*)d_in[1];
    const float* w[3][9];
    for (int li = 0; li < 3; li++)
        for (int q = 0; q < 9; q++)
            w[li][q] = (const float*)d_in[2 + li * 9 + q];

    __nv_bfloat16 *pXh, *pXl, *pW0h, *pW0l, *pW1h, *pW1l, *pW2h, *pW2l;
    __nv_bfloat16 *p0h, *p0l, *p1h, *p1l, *p2h, *p2l;
    cudaGetSymbolAddress((void**)&pXh, Xh);   cudaGetSymbolAddress((void**)&pXl, Xl);
    cudaGetSymbolAddress((void**)&pW0h, W0h); cudaGetSymbolAddress((void**)&pW0l, W0l);
    cudaGetSymbolAddress((void**)&pW1h, W1h); cudaGetSymbolAddress((void**)&pW1l, W1l);
    cudaGetSymbolAddress((void**)&pW2h, W2h); cudaGetSymbolAddress((void**)&pW2l, W2l);
    cudaGetSymbolAddress((void**)&p0h, h0h);  cudaGetSymbolAddress((void**)&p0l, h0l);
    cudaGetSymbolAddress((void**)&p1h, h1h);  cudaGetSymbolAddress((void**)&p1l, h1l);
    cudaGetSymbolAddress((void**)&p2h, h2h);  cudaGetSymbolAddress((void**)&p2l, h2l);

    cudaFuncSetAttribute((const void*)cfc_persist,
                         cudaFuncAttributeMaxDynamicSharedMemorySize, SMF);

    // zero initial hidden states (ping buffer 0) + scheduler state
    cudaMemsetAsync(p0h, 0, (size_t)BQ * H0 * sizeof(__nv_bfloat16));
    cudaMemsetAsync(p0l, 0, (size_t)BQ * H0 * sizeof(__nv_bfloat16));
    cudaMemsetAsync(p1h, 0, (size_t)BQ * H1 * sizeof(__nv_bfloat16));
    cudaMemsetAsync(p1l, 0, (size_t)BQ * H1 * sizeof(__nv_bfloat16));
    cudaMemsetAsync(p2h, 0, (size_t)BQ * H2 * sizeof(__nv_bfloat16));
    cudaMemsetAsync(p2l, 0, (size_t)BQ * H2 * sizeof(__nv_bfloat16));
    prep_sched<<<(KT * 8 + 255) / 256, 256>>>();

    // prep
    {
        size_t n = (size_t)BQ * KT * SENS;
        prep_inputs_bf<<<(unsigned)((n + 255) / 256), 256>>>(base, vis, pXh, pXl);
    }
    prep_weights3<<<(H0 * C0 + 255) / 256, 256>>>(w[0][0], w[0][2], w[0][4], w[0][6], w[0][8], pW0h, pW0l, H0, C0);
    prep_weights3<<<(H1 * C1 + 255) / 256, 256>>>(w[1][0], w[1][2], w[1][4], w[1][6], w[1][8], pW1h, pW1l, H1, C1);
    prep_weights3<<<(H2 * C2 + 255) / 256, 256>>>(w[2][0], w[2][2], w[2][4], w[2][6], w[2][8], pW2h, pW2l, H2, C2);
    prep_bts<<<2, 256>>>(w[0][5], w[0][7], w[1][5], w[1][7], w[2][5], w[2][7]);

    // one persistent launch: recurrence tiles + input-GEMM filler tiles
    cfc_persist<<<592, 128, SMF>>>(w[0][1], w[0][3],
                                   w[1][1], w[1][3],
                                   w[2][1], w[2][3]);

    // final motor-layer state: L2(63) wrote slot 0
    extract_out<<<(BQ * H2 + 255) / 256, 256>>>(p2h, p2l, (float*)d_out, BQ * H2);
}